// round 5
// baseline (speedup 1.0000x reference)
#include <cuda_runtime.h>
#include <cuda_bf16.h>

#define FDIM 128
#define SNEI 10
#define KCLU 16
#define NMAX 200704
#define BMAX 20480

typedef unsigned long long ull;

// scratch (__device__ globals per allocation rules)
__device__ float g_prod[(size_t)NMAX * FDIM];   // neigh[n,f] * coef[n,f]
__device__ float g_pdot[NMAX];                  // neigh[n] . a_neigh
__device__ float g_c2[16];
__device__ float g_comb[(size_t)BMAX * 256];
__device__ float g_part[2 * (size_t)BMAX * FDIM];

#define FFMA2(d, a, b, c) \
    asm("fma.rn.f32x2 %0, %1, %2, %3;" : "=l"(d) : "l"(a), "l"(b), "l"(c))
#define PACK2(d, lo, hi) \
    asm("mov.b64 %0, {%1, %2};" : "=l"(d) : "f"(lo), "f"(hi))
#define UNPACK2(lo, hi, v) \
    asm("mov.b64 {%0, %1}, %2;" : "=f"(lo), "=f"(hi) : "l"(v))

// ---------------------------------------------------------------------------
// c2[k] = |center_k|^2
// ---------------------------------------------------------------------------
__global__ void c2_kernel(const float* __restrict__ center, float* __restrict__ c2)
{
    int w = threadIdx.x >> 5, l = threadIdx.x & 31;  // 16 warps
    float4 v = ((const float4*)center)[w * 32 + l];
    float s = v.x * v.x + v.y * v.y + v.z * v.z + v.w * v.w;
#pragma unroll
    for (int o = 16; o; o >>= 1) s += __shfl_xor_sync(0xffffffffu, s, o);
    if (l == 0) c2[w] = s;
}

// ---------------------------------------------------------------------------
// Precompute per node n:
//   pdot[n]   = row . a_neigh
//   q[n][k]   = 1/(n2 - 2 cross[k] + 1 + c2[k])
//   prod[n,f] = row[f] * sum_k q[n][k] * mask[k][f]
// 64 nodes per block, 128 threads. rows_s stride 132 -> aligned float4,
// conflict-free in every access phase.
// ---------------------------------------------------------------------------
#define RSTR 132

__global__ __launch_bounds__(128)
void precompute_kernel(const float* __restrict__ neigh_table,
                       const float* __restrict__ center,
                       const float* __restrict__ alpha,
                       const float* __restrict__ cmask,
                       const float* __restrict__ c2g,
                       float* __restrict__ prod,
                       float* __restrict__ pdot,
                       int N)
{
    __shared__ __align__(16) float rows_s[64 * RSTR];        // 33792 B
    __shared__ __align__(16) float cen_s[16 * 128];          // 8192 B (reused)
    __shared__ __align__(16) float alp_s[128];
    __shared__ __align__(8)  float q_s[64 * 18];
    __shared__ float c2_s[16];

    int t = threadIdx.x;
    int base = blockIdx.x * 64;
    int n = t & 63, h = t >> 6;

    // mask registers for phase 3 (thread = feature t)
    ull mp[8];
#pragma unroll
    for (int kp = 0; kp < 8; kp++) {
        float m0 = cmask[(2 * kp) * FDIM + t];
        float m1 = cmask[(2 * kp + 1) * FDIM + t];
        PACK2(mp[kp], m0, m1);
    }

    // stage 64 rows + center + alpha_neigh + c2
#pragma unroll
    for (int j = 0; j < 16; j++) {
        int i = j * 128 + t;                  // float4 index over 64x128 tile
        int r = i >> 5, c = i & 31;
        float4 v = make_float4(0.f, 0.f, 0.f, 0.f);
        if (base + r < N)
            v = ((const float4*)neigh_table)[(size_t)(base + r) * 32 + c];
        *(float4*)&rows_s[r * RSTR + c * 4] = v;
    }
#pragma unroll
    for (int j = 0; j < 4; j++)
        ((float4*)cen_s)[j * 128 + t] = ((const float4*)center)[j * 128 + t];
    if (t < 32) ((float4*)alp_s)[t] = ((const float4*)alpha)[32 + t];
    if (t < 16) c2_s[t] = c2g[t];
    __syncthreads();

    // phase 2: each thread reduces half the features of node n
    ull crp[16], n2p = 0ull, adp = 0ull;
#pragma unroll
    for (int k = 0; k < 16; k++) crp[k] = 0ull;

    {
        const float4* row = (const float4*)&rows_s[n * RSTR + h * 64];
#pragma unroll 4
        for (int q = 0; q < 16; q++) {
            float4 x = row[q];
            ull xp0, xp1;
            PACK2(xp0, x.x, x.y);
            PACK2(xp1, x.z, x.w);
            ulonglong2 ap = ((const ulonglong2*)(alp_s + h * 64))[q];
            FFMA2(adp, xp0, ap.x, adp);
            FFMA2(adp, xp1, ap.y, adp);
            FFMA2(n2p, xp0, xp0, n2p);
            FFMA2(n2p, xp1, xp1, n2p);
#pragma unroll
            for (int k = 0; k < 16; k++) {
                ulonglong2 cp = ((const ulonglong2*)(cen_s + k * 128 + h * 64))[q];
                FFMA2(crp[k], xp0, cp.x, crp[k]);
                FFMA2(crp[k], xp1, cp.y, crp[k]);
            }
        }
    }

    float cr[16], n2v, adv;
    {
        float lo, hi;
#pragma unroll
        for (int k = 0; k < 16; k++) { UNPACK2(lo, hi, crp[k]); cr[k] = lo + hi; }
        UNPACK2(lo, hi, n2p); n2v = lo + hi;
        UNPACK2(lo, hi, adp); adv = lo + hi;
    }
    __syncthreads();                 // cen_s free -> reuse as partial buffer
    float* part_s = cen_s;           // 64 nodes x 19 floats (odd stride)
    if (h == 1) {
#pragma unroll
        for (int k = 0; k < 16; k++) part_s[n * 19 + k] = cr[k];
        part_s[n * 19 + 16] = n2v;
        part_s[n * 19 + 17] = adv;
    }
    __syncthreads();
    if (h == 0) {
        float n2t = n2v + part_s[n * 19 + 16];
        float adt = adv + part_s[n * 19 + 17];
        float bse = n2t + 1.0f;
#pragma unroll
        for (int k = 0; k < 16; k++) {
            float crt = cr[k] + part_s[n * 19 + k];
            float den = fmaf(-2.0f, crt, bse + c2_s[k]);
            q_s[n * 18 + k] = 1.0f / den;
        }
        if (base + n < N) pdot[base + n] = adt;
    }
    __syncthreads();

    // phase 3: thread = feature t; loop nodes
    int nlim = min(64, N - base);
    for (int nn = 0; nn < nlim; nn++) {
        const ull* qp = (const ull*)&q_s[nn * 18];
        ull acc = 0ull;
#pragma unroll
        for (int kp = 0; kp < 8; kp++)
            FFMA2(acc, qp[kp], mp[kp], acc);
        float lo, hi; UNPACK2(lo, hi, acc);
        float x = rows_s[nn * RSTR + t];
        prod[(size_t)(base + nn) * FDIM + t] = x * (lo + hi);
    }
}

// ---------------------------------------------------------------------------
// Row kernel: warp per row. Gather self + 10 prod rows, attention, aggregate.
// ---------------------------------------------------------------------------
__global__ __launch_bounds__(256)
void row_kernel(const int* __restrict__ nodes,
                const int* __restrict__ neigh_idx,
                const float* __restrict__ self_table,
                const float* __restrict__ alpha,
                const float* __restrict__ pdot,
                const float* __restrict__ prod,
                float* __restrict__ comb,
                int B)
{
    int wid = threadIdx.x >> 5, lane = threadIdx.x & 31;
    int b = blockIdx.x * 8 + wid;
    if (b >= B) return;

    int node = nodes[b];
    int idx[SNEI];
#pragma unroll
    for (int s = 0; s < SNEI; s++) idx[s] = neigh_idx[b * SNEI + s];

    float4 sf = ((const float4*)self_table)[(size_t)node * 32 + lane];
    float4 pr[SNEI];
#pragma unroll
    for (int s = 0; s < SNEI; s++)
        pr[s] = ((const float4*)prod)[(size_t)idx[s] * 32 + lane];
    float pd[SNEI];
#pragma unroll
    for (int s = 0; s < SNEI; s++) pd[s] = pdot[idx[s]];

    float4 al = ((const float4*)alpha)[lane];
    float d = sf.x * al.x + sf.y * al.y + sf.z * al.z + sf.w * al.w;
#pragma unroll
    for (int o = 16; o; o >>= 1) d += __shfl_xor_sync(0xffffffffu, d, o);

    float e[SNEI], sum = 0.f;
#pragma unroll
    for (int s = 0; s < SNEI; s++) {
        float l = fmaxf(d + pd[s], 0.f);
        e[s] = __expf(l);
        sum += e[s];
    }
    float inv = 1.0f / sum;

    float4 agg = make_float4(0.f, 0.f, 0.f, 0.f);
#pragma unroll
    for (int s = 0; s < SNEI; s++) {
        float w = e[s] * inv;
        agg.x = fmaf(w, pr[s].x, agg.x);
        agg.y = fmaf(w, pr[s].y, agg.y);
        agg.z = fmaf(w, pr[s].z, agg.z);
        agg.w = fmaf(w, pr[s].w, agg.w);
    }

    ((float4*)comb)[(size_t)b * 64 + lane]      = sf;
    ((float4*)comb)[(size_t)b * 64 + 32 + lane] = agg;
}

// ---------------------------------------------------------------------------
// GEMM split-K, double-buffered:
//   part[ks][b][e] = comb[b, ks*128:(ks+1)*128] @ W[e, same]^T
// BM=128, BN=128, BK=16, 256 threads, 8x8 f32x2 microtile, 2-deep smem pipe.
// ---------------------------------------------------------------------------
#define GBM 128
#define GBK 16
#define KTILES 8   // 128 / GBK per k-slice

__global__ __launch_bounds__(256, 2)
void gemm_part_kernel(const float* __restrict__ A,
                      const float* __restrict__ W,
                      float* __restrict__ part,
                      int Brows)
{
    __shared__ __align__(16) float As[2][GBK][GBM];
    __shared__ __align__(16) float Bs[2][GBK][FDIM];

    int tid = threadIdx.x;
    int tx = tid & 15;        // 16 col groups of 8
    int ty = tid >> 4;        // 16 row groups of 8
    int row0 = blockIdx.x * GBM;
    int kbase = blockIdx.y * 128;

    // load indices: 512 float4 per tile, 2 per thread
    int la_r0 = tid >> 1,          la_c0 = (tid & 1) * 4;        // A: r in 0..127, c4 0/4
    int la_r1 = tid >> 1,          la_c1 = (tid & 1) * 4 + 8;    // second half of 16 cols
    int lb_n0 = tid >> 1,          lb_c0 = (tid & 1) * 4;
    int lb_n1 = tid >> 1,          lb_c1 = (tid & 1) * 4 + 8;

    ull acc[8][4];
#pragma unroll
    for (int i = 0; i < 8; i++)
#pragma unroll
        for (int p = 0; p < 4; p++) acc[i][p] = 0ull;

    float4 ra0, ra1, rb0, rb1;

    // prefetch tile 0
    {
        int k0 = kbase;
        ra0 = ra1 = make_float4(0.f, 0.f, 0.f, 0.f);
        if (row0 + la_r0 < Brows) {
            ra0 = *(const float4*)&A[(size_t)(row0 + la_r0) * 256 + k0 + la_c0];
            ra1 = *(const float4*)&A[(size_t)(row0 + la_r1) * 256 + k0 + la_c1];
        }
        rb0 = *(const float4*)&W[(size_t)lb_n0 * 256 + k0 + lb_c0];
        rb1 = *(const float4*)&W[(size_t)lb_n1 * 256 + k0 + lb_c1];
    }
    // store tile 0
    {
        As[0][la_c0 + 0][la_r0] = ra0.x; As[0][la_c0 + 1][la_r0] = ra0.y;
        As[0][la_c0 + 2][la_r0] = ra0.z; As[0][la_c0 + 3][la_r0] = ra0.w;
        As[0][la_c1 + 0][la_r1] = ra1.x; As[0][la_c1 + 1][la_r1] = ra1.y;
        As[0][la_c1 + 2][la_r1] = ra1.z; As[0][la_c1 + 3][la_r1] = ra1.w;
        Bs[0][lb_c0 + 0][lb_n0] = rb0.x; Bs[0][lb_c0 + 1][lb_n0] = rb0.y;
        Bs[0][lb_c0 + 2][lb_n0] = rb0.z; Bs[0][lb_c0 + 3][lb_n0] = rb0.w;
        Bs[0][lb_c1 + 0][lb_n1] = rb1.x; Bs[0][lb_c1 + 1][lb_n1] = rb1.y;
        Bs[0][lb_c1 + 2][lb_n1] = rb1.z; Bs[0][lb_c1 + 3][lb_n1] = rb1.w;
    }
    __syncthreads();

    int buf = 0;
#pragma unroll
    for (int kt = 0; kt < KTILES; kt++) {
        // prefetch next tile (LDGs issue before the FFMA stream)
        if (kt + 1 < KTILES) {
            int k0 = kbase + (kt + 1) * GBK;
            ra0 = ra1 = make_float4(0.f, 0.f, 0.f, 0.f);
            if (row0 + la_r0 < Brows) {
                ra0 = *(const float4*)&A[(size_t)(row0 + la_r0) * 256 + k0 + la_c0];
                ra1 = *(const float4*)&A[(size_t)(row0 + la_r1) * 256 + k0 + la_c1];
            }
            rb0 = *(const float4*)&W[(size_t)lb_n0 * 256 + k0 + lb_c0];
            rb1 = *(const float4*)&W[(size_t)lb_n1 * 256 + k0 + lb_c1];
        }

        // compute current tile
#pragma unroll
        for (int kk = 0; kk < GBK; kk++) {
            float4 a0 = *(const float4*)&As[buf][kk][ty * 8];
            float4 a1 = *(const float4*)&As[buf][kk][ty * 8 + 4];
            const ull* bp = (const ull*)&Bs[buf][kk][tx * 8];
            ull b0 = bp[0], b1 = bp[1], b2 = bp[2], b3 = bp[3];
            float av[8] = {a0.x, a0.y, a0.z, a0.w, a1.x, a1.y, a1.z, a1.w};
#pragma unroll
            for (int i = 0; i < 8; i++) {
                ull ap;
                PACK2(ap, av[i], av[i]);
                FFMA2(acc[i][0], ap, b0, acc[i][0]);
                FFMA2(acc[i][1], ap, b1, acc[i][1]);
                FFMA2(acc[i][2], ap, b2, acc[i][2]);
                FFMA2(acc[i][3], ap, b3, acc[i][3]);
            }
        }

        if (kt + 1 < KTILES) {
            int nb = buf ^ 1;
            __syncthreads();   // everyone done reading buf^1 from 2 tiles ago
            As[nb][la_c0 + 0][la_r0] = ra0.x; As[nb][la_c0 + 1][la_r0] = ra0.y;
            As[nb][la_c0 + 2][la_r0] = ra0.z; As[nb][la_c0 + 3][la_r0] = ra0.w;
            As[nb][la_c1 + 0][la_r1] = ra1.x; As[nb][la_c1 + 1][la_r1] = ra1.y;
            As[nb][la_c1 + 2][la_r1] = ra1.z; As[nb][la_c1 + 3][la_r1] = ra1.w;
            Bs[nb][lb_c0 + 0][lb_n0] = rb0.x; Bs[nb][lb_c0 + 1][lb_n0] = rb0.y;
            Bs[nb][lb_c0 + 2][lb_n0] = rb0.z; Bs[nb][lb_c0 + 3][lb_n0] = rb0.w;
            Bs[nb][lb_c1 + 0][lb_n1] = rb1.x; Bs[nb][lb_c1 + 1][lb_n1] = rb1.y;
            Bs[nb][lb_c1 + 2][lb_n1] = rb1.z; Bs[nb][lb_c1 + 3][lb_n1] = rb1.w;
            __syncthreads();
            buf = nb;
        }
    }

    float* dst = part + (size_t)blockIdx.y * BMAX * FDIM;
#pragma unroll
    for (int i = 0; i < 8; i++) {
        int r = row0 + ty * 8 + i;
        if (r < Brows) {
            float o[8];
#pragma unroll
            for (int p = 0; p < 4; p++)
                UNPACK2(o[2 * p], o[2 * p + 1], acc[i][p]);
            *(float4*)&dst[(size_t)r * FDIM + tx * 8]     = make_float4(o[0], o[1], o[2], o[3]);
            *(float4*)&dst[(size_t)r * FDIM + tx * 8 + 4] = make_float4(o[4], o[5], o[6], o[7]);
        }
    }
}

// ---------------------------------------------------------------------------
__global__ __launch_bounds__(256)
void combine_kernel(const float* __restrict__ part, float* __restrict__ out, int total4)
{
    int i = blockIdx.x * 256 + threadIdx.x;
    if (i >= total4) return;
    float4 a = ((const float4*)part)[i];
    float4 b = ((const float4*)(part + (size_t)BMAX * FDIM))[i];
    float4 o;
    o.x = fmaxf(a.x + b.x, 0.f);
    o.y = fmaxf(a.y + b.y, 0.f);
    o.z = fmaxf(a.z + b.z, 0.f);
    o.w = fmaxf(a.w + b.w, 0.f);
    ((float4*)out)[i] = o;
}

// ---------------------------------------------------------------------------
extern "C" void kernel_launch(void* const* d_in, const int* in_sizes, int n_in,
                              void* d_out, int out_size)
{
    const int*   nodes      = (const int*)d_in[0];
    const int*   neigh_idx  = (const int*)d_in[1];
    const float* self_table = (const float*)d_in[2];
    const float* neigh_tab  = (const float*)d_in[3];
    const float* center     = (const float*)d_in[4];
    const float* cmask      = (const float*)d_in[5];
    const float* weight     = (const float*)d_in[6];
    const float* alpha      = (const float*)d_in[7];
    float*       out        = (float*)d_out;

    int B = in_sizes[0];
    int N = in_sizes[3] / FDIM;

    float *prod, *pd, *c2, *comb, *part;
    cudaGetSymbolAddress((void**)&prod, g_prod);
    cudaGetSymbolAddress((void**)&pd,   g_pdot);
    cudaGetSymbolAddress((void**)&c2,   g_c2);
    cudaGetSymbolAddress((void**)&comb, g_comb);
    cudaGetSymbolAddress((void**)&part, g_part);

    c2_kernel<<<1, 512>>>(center, c2);
    precompute_kernel<<<(N + 63) / 64, 128>>>(neigh_tab, center, alpha, cmask,
                                              c2, prod, pd, N);
    row_kernel<<<(B + 7) / 8, 256>>>(nodes, neigh_idx, self_table, alpha,
                                     pd, prod, comb, B);
    dim3 gg((B + GBM - 1) / GBM, 2);
    gemm_part_kernel<<<gg, 256>>>(comb, weight, part, B);
    combine_kernel<<<(B * 32 + 255) / 256, 256>>>(part, out, B * 32);
}

// round 7
// speedup vs baseline: 1.0581x; 1.0581x over previous
#include <cuda_runtime.h>
#include <cuda_bf16.h>
#include <mma.h>
#include <cstdint>

using namespace nvcuda;

#define FDIM 128
#define SNEI 10
#define KCLU 16
#define NMAX 200704
#define BMAX 20480

typedef unsigned long long ull;

// scratch (__device__ globals per allocation rules)
__device__ float         g_pdot[NMAX];
__device__ float         g_c2[16];
__device__ float         g_prod[(size_t)NMAX * FDIM];
__device__ __nv_bfloat16 g_comb_hi[(size_t)BMAX * 256];
__device__ __nv_bfloat16 g_comb_lo[(size_t)BMAX * 256];
__device__ __nv_bfloat16 g_w_hi[128 * 256];
__device__ __nv_bfloat16 g_w_lo[128 * 256];

#define FFMA2(d, a, b, c) \
    asm("fma.rn.f32x2 %0, %1, %2, %3;" : "=l"(d) : "l"(a), "l"(b), "l"(c))
#define PACK2(d, lo, hi) \
    asm("mov.b64 %0, {%1, %2};" : "=l"(d) : "f"(lo), "f"(hi))
#define UNPACK2(lo, hi, v) \
    asm("mov.b64 {%0, %1}, %2;" : "=f"(lo), "=f"(hi) : "l"(v))

// ---------------------------------------------------------------------------
// c2[k] = |center_k|^2
// ---------------------------------------------------------------------------
__global__ void c2_kernel(const float* __restrict__ center, float* __restrict__ c2)
{
    int w = threadIdx.x >> 5, l = threadIdx.x & 31;
    float4 v = ((const float4*)center)[w * 32 + l];
    float s = v.x * v.x + v.y * v.y + v.z * v.z + v.w * v.w;
#pragma unroll
    for (int o = 16; o; o >>= 1) s += __shfl_xor_sync(0xffffffffu, s, o);
    if (l == 0) c2[w] = s;
}

// ---------------------------------------------------------------------------
// weight split fp32 -> bf16 hi/lo
// ---------------------------------------------------------------------------
__global__ void wsplit_kernel(const float* __restrict__ w,
                              __nv_bfloat16* __restrict__ wh,
                              __nv_bfloat16* __restrict__ wl)
{
    int i = blockIdx.x * 256 + threadIdx.x;
    if (i < 128 * 256) {
        float v = w[i];
        __nv_bfloat16 h = __float2bfloat16(v);
        wh[i] = h;
        wl[i] = __float2bfloat16(v - __bfloat162float(h));
    }
}

// ---------------------------------------------------------------------------
// Precompute per node (round-4 proven version)
// ---------------------------------------------------------------------------
#define RSTR 132

__global__ __launch_bounds__(128)
void precompute_kernel(const float* __restrict__ neigh_table,
                       const float* __restrict__ center,
                       const float* __restrict__ alpha,
                       const float* __restrict__ cmask,
                       const float* __restrict__ c2g,
                       float* __restrict__ prod,
                       float* __restrict__ pdot,
                       int N)
{
    __shared__ __align__(16) float rows_s[64 * RSTR];
    __shared__ __align__(16) float cen_s[16 * 128];
    __shared__ __align__(16) float alp_s[128];
    __shared__ __align__(8)  float q_s[64 * 18];
    __shared__ float c2_s[16];

    int t = threadIdx.x;
    int base = blockIdx.x * 64;
    int n = t & 63, h = t >> 6;

    ull mp[8];
#pragma unroll
    for (int kp = 0; kp < 8; kp++) {
        float m0 = cmask[(2 * kp) * FDIM + t];
        float m1 = cmask[(2 * kp + 1) * FDIM + t];
        PACK2(mp[kp], m0, m1);
    }

#pragma unroll
    for (int j = 0; j < 16; j++) {
        int i = j * 128 + t;
        int r = i >> 5, c = i & 31;
        float4 v = make_float4(0.f, 0.f, 0.f, 0.f);
        if (base + r < N)
            v = ((const float4*)neigh_table)[(size_t)(base + r) * 32 + c];
        *(float4*)&rows_s[r * RSTR + c * 4] = v;
    }
#pragma unroll
    for (int j = 0; j < 4; j++)
        ((float4*)cen_s)[j * 128 + t] = ((const float4*)center)[j * 128 + t];
    if (t < 32) ((float4*)alp_s)[t] = ((const float4*)alpha)[32 + t];
    if (t < 16) c2_s[t] = c2g[t];
    __syncthreads();

    ull crp[16], n2p = 0ull, adp = 0ull;
#pragma unroll
    for (int k = 0; k < 16; k++) crp[k] = 0ull;

    {
        const float4* row = (const float4*)&rows_s[n * RSTR + h * 64];
#pragma unroll 4
        for (int q = 0; q < 16; q++) {
            float4 x = row[q];
            ull xp0, xp1;
            PACK2(xp0, x.x, x.y);
            PACK2(xp1, x.z, x.w);
            ulonglong2 ap = ((const ulonglong2*)(alp_s + h * 64))[q];
            FFMA2(adp, xp0, ap.x, adp);
            FFMA2(adp, xp1, ap.y, adp);
            FFMA2(n2p, xp0, xp0, n2p);
            FFMA2(n2p, xp1, xp1, n2p);
#pragma unroll
            for (int k = 0; k < 16; k++) {
                ulonglong2 cp = ((const ulonglong2*)(cen_s + k * 128 + h * 64))[q];
                FFMA2(crp[k], xp0, cp.x, crp[k]);
                FFMA2(crp[k], xp1, cp.y, crp[k]);
            }
        }
    }

    float cr[16], n2v, adv;
    {
        float lo, hi;
#pragma unroll
        for (int k = 0; k < 16; k++) { UNPACK2(lo, hi, crp[k]); cr[k] = lo + hi; }
        UNPACK2(lo, hi, n2p); n2v = lo + hi;
        UNPACK2(lo, hi, adp); adv = lo + hi;
    }
    __syncthreads();
    float* part_s = cen_s;
    if (h == 1) {
#pragma unroll
        for (int k = 0; k < 16; k++) part_s[n * 19 + k] = cr[k];
        part_s[n * 19 + 16] = n2v;
        part_s[n * 19 + 17] = adv;
    }
    __syncthreads();
    if (h == 0) {
        float n2t = n2v + part_s[n * 19 + 16];
        float adt = adv + part_s[n * 19 + 17];
        float bse = n2t + 1.0f;
#pragma unroll
        for (int k = 0; k < 16; k++) {
            float crt = cr[k] + part_s[n * 19 + k];
            float den = fmaf(-2.0f, crt, bse + c2_s[k]);
            q_s[n * 18 + k] = 1.0f / den;
        }
        if (base + n < N) pdot[base + n] = adt;
    }
    __syncthreads();

    int nlim = min(64, N - base);
    for (int nn = 0; nn < nlim; nn++) {
        const ull* qp = (const ull*)&q_s[nn * 18];
        ull acc = 0ull;
#pragma unroll
        for (int kp = 0; kp < 8; kp++)
            FFMA2(acc, qp[kp], mp[kp], acc);
        float lo, hi; UNPACK2(lo, hi, acc);
        float x = rows_s[nn * RSTR + t];
        prod[(size_t)(base + nn) * FDIM + t] = x * (lo + hi);
    }
}

// ---------------------------------------------------------------------------
// Row kernel: warp per row; outputs combined features as bf16 hi/lo splits.
// ---------------------------------------------------------------------------
__global__ __launch_bounds__(256)
void row_kernel(const int* __restrict__ nodes,
                const int* __restrict__ neigh_idx,
                const float* __restrict__ self_table,
                const float* __restrict__ alpha,
                const float* __restrict__ pdot,
                const float* __restrict__ prod,
                __nv_bfloat16* __restrict__ comb_hi,
                __nv_bfloat16* __restrict__ comb_lo,
                int B)
{
    int wid = threadIdx.x >> 5, lane = threadIdx.x & 31;
    int b = blockIdx.x * 8 + wid;
    if (b >= B) return;

    int node = nodes[b];
    int idx[SNEI];
#pragma unroll
    for (int s = 0; s < SNEI; s++) idx[s] = neigh_idx[b * SNEI + s];

    float4 sf = ((const float4*)self_table)[(size_t)node * 32 + lane];
    float4 pr[SNEI];
#pragma unroll
    for (int s = 0; s < SNEI; s++)
        pr[s] = ((const float4*)prod)[(size_t)idx[s] * 32 + lane];
    float pd[SNEI];
#pragma unroll
    for (int s = 0; s < SNEI; s++) pd[s] = pdot[idx[s]];

    float4 al = ((const float4*)alpha)[lane];
    float d = sf.x * al.x + sf.y * al.y + sf.z * al.z + sf.w * al.w;
#pragma unroll
    for (int o = 16; o; o >>= 1) d += __shfl_xor_sync(0xffffffffu, d, o);

    float e[SNEI], sum = 0.f;
#pragma unroll
    for (int s = 0; s < SNEI; s++) {
        float l = fmaxf(d + pd[s], 0.f);
        e[s] = __expf(l);
        sum += e[s];
    }
    float inv = 1.0f / sum;

    float4 agg = make_float4(0.f, 0.f, 0.f, 0.f);
#pragma unroll
    for (int s = 0; s < SNEI; s++) {
        float w = e[s] * inv;
        agg.x = fmaf(w, pr[s].x, agg.x);
        agg.y = fmaf(w, pr[s].y, agg.y);
        agg.z = fmaf(w, pr[s].z, agg.z);
        agg.w = fmaf(w, pr[s].w, agg.w);
    }

    float v[8] = {sf.x, sf.y, sf.z, sf.w, agg.x, agg.y, agg.z, agg.w};
    __nv_bfloat16 hh[8], ll[8];
#pragma unroll
    for (int i = 0; i < 8; i++) {
        hh[i] = __float2bfloat16(v[i]);
        ll[i] = __float2bfloat16(v[i] - __bfloat162float(hh[i]));
    }
    __nv_bfloat162* ch = (__nv_bfloat162*)(comb_hi + (size_t)b * 256);
    __nv_bfloat162* cl = (__nv_bfloat162*)(comb_lo + (size_t)b * 256);
    ch[lane * 2]          = __halves2bfloat162(hh[0], hh[1]);
    ch[lane * 2 + 1]      = __halves2bfloat162(hh[2], hh[3]);
    ch[64 + lane * 2]     = __halves2bfloat162(hh[4], hh[5]);
    ch[64 + lane * 2 + 1] = __halves2bfloat162(hh[6], hh[7]);
    cl[lane * 2]          = __halves2bfloat162(ll[0], ll[1]);
    cl[lane * 2 + 1]      = __halves2bfloat162(ll[2], ll[3]);
    cl[64 + lane * 2]     = __halves2bfloat162(ll[4], ll[5]);
    cl[64 + lane * 2 + 1] = __halves2bfloat162(ll[6], ll[7]);
}

// ---------------------------------------------------------------------------
// wmma bf16 GEMM: out = relu(Aext @ Wext^T), Aext = [Ah|Al|Ah], Wext = [Wh|Wh|Wl]
// K=768, BM=128, BN=128, BK=32, 256 threads = 8 warps (2x4, 64x32 warp tiles).
// ReLU applied on accumulator fragments (elementwise, order-free), stored
// directly to gmem. B % 16 == 0 -> whole-tile row guards.
// ---------------------------------------------------------------------------
#define WSTR 40   // smem row stride in bf16 (80B, 16B-aligned)

__global__ __launch_bounds__(256, 1)
void gemm_wmma_kernel(const __nv_bfloat16* __restrict__ Ah,
                      const __nv_bfloat16* __restrict__ Al,
                      const __nv_bfloat16* __restrict__ Wh,
                      const __nv_bfloat16* __restrict__ Wl,
                      float* __restrict__ out,
                      int Brows)
{
    __shared__ __align__(16) __nv_bfloat16 As[128 * WSTR];
    __shared__ __align__(16) __nv_bfloat16 Ws[128 * WSTR];

    int tid = threadIdx.x;
    int w = tid >> 5;
    int wm = w & 1, wn = w >> 1;      // 2 x 4 warp grid
    int row0 = blockIdx.x * 128;
    int m0 = wm * 64, n0 = wn * 32;

    wmma::fragment<wmma::accumulator, 16, 16, 16, float> acc[4][2];
#pragma unroll
    for (int i = 0; i < 4; i++)
#pragma unroll
        for (int j = 0; j < 2; j++)
            wmma::fill_fragment(acc[i][j], 0.0f);

    for (int kt = 0; kt < 24; kt++) {
        int seg = kt >> 3;                 // 0,1,2
        int kcol = (kt & 7) * 32;          // column within 256-wide segment
        const __nv_bfloat16* Asrc = (seg == 1) ? Al : Ah;
        const __nv_bfloat16* Wsrc = (seg == 2) ? Wl : Wh;

        // stage A tile (128x32) and W tile (128x32): 2 float4 each per thread
#pragma unroll
        for (int j = 0; j < 2; j++) {
            int i = j * 256 + tid;
            int r = i >> 2, c8 = (i & 3) * 8;
            float4 av = make_float4(0.f, 0.f, 0.f, 0.f);
            if (row0 + r < Brows)
                av = *(const float4*)&Asrc[(size_t)(row0 + r) * 256 + kcol + c8];
            *(float4*)&As[r * WSTR + c8] = av;
            float4 wv = *(const float4*)&Wsrc[(size_t)r * 256 + kcol + c8];
            *(float4*)&Ws[r * WSTR + c8] = wv;
        }
        __syncthreads();

#pragma unroll
        for (int kk = 0; kk < 32; kk += 16) {
            wmma::fragment<wmma::matrix_a, 16, 16, 16, __nv_bfloat16, wmma::row_major> af[4];
            wmma::fragment<wmma::matrix_b, 16, 16, 16, __nv_bfloat16, wmma::col_major> bf[2];
#pragma unroll
            for (int i = 0; i < 4; i++)
                wmma::load_matrix_sync(af[i], &As[(m0 + i * 16) * WSTR + kk], WSTR);
#pragma unroll
            for (int j = 0; j < 2; j++)
                wmma::load_matrix_sync(bf[j], &Ws[(n0 + j * 16) * WSTR + kk], WSTR);
#pragma unroll
            for (int i = 0; i < 4; i++)
#pragma unroll
                for (int j = 0; j < 2; j++)
                    wmma::mma_sync(acc[i][j], af[i], bf[j], acc[i][j]);
        }
        __syncthreads();
    }

    // relu on fragments (elementwise) + direct store
#pragma unroll
    for (int i = 0; i < 4; i++) {
        int gr = row0 + m0 + i * 16;
        if (gr < Brows) {   // Brows % 16 == 0 -> whole tile valid
#pragma unroll
            for (int j = 0; j < 2; j++) {
#pragma unroll
                for (int e = 0; e < acc[i][j].num_elements; e++)
                    acc[i][j].x[e] = fmaxf(acc[i][j].x[e], 0.0f);
                wmma::store_matrix_sync(&out[(size_t)gr * FDIM + n0 + j * 16],
                                        acc[i][j], FDIM, wmma::mem_row_major);
            }
        }
    }
}

// ---------------------------------------------------------------------------
extern "C" void kernel_launch(void* const* d_in, const int* in_sizes, int n_in,
                              void* d_out, int out_size)
{
    const int*   nodes      = (const int*)d_in[0];
    const int*   neigh_idx  = (const int*)d_in[1];
    const float* self_table = (const float*)d_in[2];
    const float* neigh_tab  = (const float*)d_in[3];
    const float* center     = (const float*)d_in[4];
    const float* cmask      = (const float*)d_in[5];
    const float* weight     = (const float*)d_in[6];
    const float* alpha      = (const float*)d_in[7];
    float*       out        = (float*)d_out;

    int B = in_sizes[0];
    int N = in_sizes[3] / FDIM;

    float *prod, *pd, *c2;
    __nv_bfloat16 *ch, *cl, *wh, *wl;
    cudaGetSymbolAddress((void**)&prod, g_prod);
    cudaGetSymbolAddress((void**)&pd,   g_pdot);
    cudaGetSymbolAddress((void**)&c2,   g_c2);
    cudaGetSymbolAddress((void**)&ch,   g_comb_hi);
    cudaGetSymbolAddress((void**)&cl,   g_comb_lo);
    cudaGetSymbolAddress((void**)&wh,   g_w_hi);
    cudaGetSymbolAddress((void**)&wl,   g_w_lo);

    c2_kernel<<<1, 512>>>(center, c2);
    wsplit_kernel<<<128, 256>>>(weight, wh, wl);
    precompute_kernel<<<(N + 63) / 64, 128>>>(neigh_tab, center, alpha, cmask,
                                              c2, prod, pd, N);
    row_kernel<<<(B + 7) / 8, 256>>>(nodes, neigh_idx, self_table, alpha,
                                     pd, prod, ch, cl, B);
    gemm_wmma_kernel<<<(B + 127) / 128, 256>>>(ch, cl, wh, wl, out, B);
}

// round 8
// speedup vs baseline: 1.3322x; 1.2590x over previous
#include <cuda_runtime.h>
#include <cuda_bf16.h>
#include <cuda_fp16.h>
#include <mma.h>
#include <cstdint>

using namespace nvcuda;

#define FDIM 128
#define SNEI 10
#define KCLU 16
#define NMAX 200704
#define BMAX 20480

typedef unsigned long long ull;

// scratch (__device__ globals per allocation rules)
__device__ float         g_pdot[NMAX];
__device__ float         g_c2[16];
__device__ __half        g_prod[(size_t)NMAX * FDIM];      // fp16: halves traffic
__device__ __nv_bfloat16 g_comb_hi[(size_t)BMAX * 256];
__device__ __nv_bfloat16 g_comb_lo[(size_t)BMAX * 256];
__device__ __nv_bfloat16 g_w_hi[128 * 256];
__device__ __nv_bfloat16 g_w_lo[128 * 256];

#define FFMA2(d, a, b, c) \
    asm("fma.rn.f32x2 %0, %1, %2, %3;" : "=l"(d) : "l"(a), "l"(b), "l"(c))
#define PACK2(d, lo, hi) \
    asm("mov.b64 %0, {%1, %2};" : "=l"(d) : "f"(lo), "f"(hi))
#define UNPACK2(lo, hi, v) \
    asm("mov.b64 {%0, %1}, %2;" : "=f"(lo), "=f"(hi) : "l"(v))

// ---------------------------------------------------------------------------
// c2[k] = |center_k|^2
// ---------------------------------------------------------------------------
__global__ void c2_kernel(const float* __restrict__ center, float* __restrict__ c2)
{
    int w = threadIdx.x >> 5, l = threadIdx.x & 31;
    float4 v = ((const float4*)center)[w * 32 + l];
    float s = v.x * v.x + v.y * v.y + v.z * v.z + v.w * v.w;
#pragma unroll
    for (int o = 16; o; o >>= 1) s += __shfl_xor_sync(0xffffffffu, s, o);
    if (l == 0) c2[w] = s;
}

// ---------------------------------------------------------------------------
// weight split fp32 -> bf16 hi/lo
// ---------------------------------------------------------------------------
__global__ void wsplit_kernel(const float* __restrict__ w,
                              __nv_bfloat16* __restrict__ wh,
                              __nv_bfloat16* __restrict__ wl)
{
    int i = blockIdx.x * 256 + threadIdx.x;
    if (i < 128 * 256) {
        float v = w[i];
        __nv_bfloat16 h = __float2bfloat16(v);
        wh[i] = h;
        wl[i] = __float2bfloat16(v - __bfloat162float(h));
    }
}

// ---------------------------------------------------------------------------
// Precompute per node; prod written as fp16.
// ---------------------------------------------------------------------------
#define RSTR 132

__global__ __launch_bounds__(128)
void precompute_kernel(const float* __restrict__ neigh_table,
                       const float* __restrict__ center,
                       const float* __restrict__ alpha,
                       const float* __restrict__ cmask,
                       const float* __restrict__ c2g,
                       __half* __restrict__ prod,
                       float* __restrict__ pdot,
                       int N)
{
    __shared__ __align__(16) float rows_s[64 * RSTR];
    __shared__ __align__(16) float cen_s[16 * 128];
    __shared__ __align__(16) float alp_s[128];
    __shared__ __align__(8)  float q_s[64 * 18];
    __shared__ float c2_s[16];

    int t = threadIdx.x;
    int base = blockIdx.x * 64;
    int n = t & 63, h = t >> 6;

    ull mp[8];
#pragma unroll
    for (int kp = 0; kp < 8; kp++) {
        float m0 = cmask[(2 * kp) * FDIM + t];
        float m1 = cmask[(2 * kp + 1) * FDIM + t];
        PACK2(mp[kp], m0, m1);
    }

#pragma unroll
    for (int j = 0; j < 16; j++) {
        int i = j * 128 + t;
        int r = i >> 5, c = i & 31;
        float4 v = make_float4(0.f, 0.f, 0.f, 0.f);
        if (base + r < N)
            v = ((const float4*)neigh_table)[(size_t)(base + r) * 32 + c];
        *(float4*)&rows_s[r * RSTR + c * 4] = v;
    }
#pragma unroll
    for (int j = 0; j < 4; j++)
        ((float4*)cen_s)[j * 128 + t] = ((const float4*)center)[j * 128 + t];
    if (t < 32) ((float4*)alp_s)[t] = ((const float4*)alpha)[32 + t];
    if (t < 16) c2_s[t] = c2g[t];
    __syncthreads();

    ull crp[16], n2p = 0ull, adp = 0ull;
#pragma unroll
    for (int k = 0; k < 16; k++) crp[k] = 0ull;

    {
        const float4* row = (const float4*)&rows_s[n * RSTR + h * 64];
#pragma unroll 4
        for (int q = 0; q < 16; q++) {
            float4 x = row[q];
            ull xp0, xp1;
            PACK2(xp0, x.x, x.y);
            PACK2(xp1, x.z, x.w);
            ulonglong2 ap = ((const ulonglong2*)(alp_s + h * 64))[q];
            FFMA2(adp, xp0, ap.x, adp);
            FFMA2(adp, xp1, ap.y, adp);
            FFMA2(n2p, xp0, xp0, n2p);
            FFMA2(n2p, xp1, xp1, n2p);
#pragma unroll
            for (int k = 0; k < 16; k++) {
                ulonglong2 cp = ((const ulonglong2*)(cen_s + k * 128 + h * 64))[q];
                FFMA2(crp[k], xp0, cp.x, crp[k]);
                FFMA2(crp[k], xp1, cp.y, crp[k]);
            }
        }
    }

    float cr[16], n2v, adv;
    {
        float lo, hi;
#pragma unroll
        for (int k = 0; k < 16; k++) { UNPACK2(lo, hi, crp[k]); cr[k] = lo + hi; }
        UNPACK2(lo, hi, n2p); n2v = lo + hi;
        UNPACK2(lo, hi, adp); adv = lo + hi;
    }
    __syncthreads();
    float* part_s = cen_s;
    if (h == 1) {
#pragma unroll
        for (int k = 0; k < 16; k++) part_s[n * 19 + k] = cr[k];
        part_s[n * 19 + 16] = n2v;
        part_s[n * 19 + 17] = adv;
    }
    __syncthreads();
    if (h == 0) {
        float n2t = n2v + part_s[n * 19 + 16];
        float adt = adv + part_s[n * 19 + 17];
        float bse = n2t + 1.0f;
#pragma unroll
        for (int k = 0; k < 16; k++) {
            float crt = cr[k] + part_s[n * 19 + k];
            float den = fmaf(-2.0f, crt, bse + c2_s[k]);
            q_s[n * 18 + k] = 1.0f / den;
        }
        if (base + n < N) pdot[base + n] = adt;
    }
    __syncthreads();

    int nlim = min(64, N - base);
    for (int nn = 0; nn < nlim; nn++) {
        const ull* qp = (const ull*)&q_s[nn * 18];
        ull acc = 0ull;
#pragma unroll
        for (int kp = 0; kp < 8; kp++)
            FFMA2(acc, qp[kp], mp[kp], acc);
        float lo, hi; UNPACK2(lo, hi, acc);
        float x = rows_s[nn * RSTR + t];
        prod[(size_t)(base + nn) * FDIM + t] = __float2half(x * (lo + hi));
    }
}

// ---------------------------------------------------------------------------
// Row kernel: warp per row; gathers fp16 prod rows; emits bf16 hi/lo comb.
// ---------------------------------------------------------------------------
__global__ __launch_bounds__(256)
void row_kernel(const int* __restrict__ nodes,
                const int* __restrict__ neigh_idx,
                const float* __restrict__ self_table,
                const float* __restrict__ alpha,
                const float* __restrict__ pdot,
                const __half* __restrict__ prod,
                __nv_bfloat16* __restrict__ comb_hi,
                __nv_bfloat16* __restrict__ comb_lo,
                int B)
{
    int wid = threadIdx.x >> 5, lane = threadIdx.x & 31;
    int b = blockIdx.x * 8 + wid;
    if (b >= B) return;

    int node = nodes[b];
    int idx[SNEI];
#pragma unroll
    for (int s = 0; s < SNEI; s++) idx[s] = neigh_idx[b * SNEI + s];

    float4 sf = ((const float4*)self_table)[(size_t)node * 32 + lane];
    uint2 praw[SNEI];
#pragma unroll
    for (int s = 0; s < SNEI; s++)
        praw[s] = ((const uint2*)(prod + (size_t)idx[s] * FDIM))[lane];
    float pd[SNEI];
#pragma unroll
    for (int s = 0; s < SNEI; s++) pd[s] = pdot[idx[s]];

    float4 al = ((const float4*)alpha)[lane];
    float d = sf.x * al.x + sf.y * al.y + sf.z * al.z + sf.w * al.w;
#pragma unroll
    for (int o = 16; o; o >>= 1) d += __shfl_xor_sync(0xffffffffu, d, o);

    float e[SNEI], sum = 0.f;
#pragma unroll
    for (int s = 0; s < SNEI; s++) {
        float l = fmaxf(d + pd[s], 0.f);
        e[s] = __expf(l);
        sum += e[s];
    }
    float inv = 1.0f / sum;

    float4 agg = make_float4(0.f, 0.f, 0.f, 0.f);
#pragma unroll
    for (int s = 0; s < SNEI; s++) {
        float w = e[s] * inv;
        float2 f01 = __half22float2(*(const __half2*)&praw[s].x);
        float2 f23 = __half22float2(*(const __half2*)&praw[s].y);
        agg.x = fmaf(w, f01.x, agg.x);
        agg.y = fmaf(w, f01.y, agg.y);
        agg.z = fmaf(w, f23.x, agg.z);
        agg.w = fmaf(w, f23.y, agg.w);
    }

    float v[8] = {sf.x, sf.y, sf.z, sf.w, agg.x, agg.y, agg.z, agg.w};
    __nv_bfloat16 hh[8], ll[8];
#pragma unroll
    for (int i = 0; i < 8; i++) {
        hh[i] = __float2bfloat16(v[i]);
        ll[i] = __float2bfloat16(v[i] - __bfloat162float(hh[i]));
    }
    __nv_bfloat162* ch = (__nv_bfloat162*)(comb_hi + (size_t)b * 256);
    __nv_bfloat162* cl = (__nv_bfloat162*)(comb_lo + (size_t)b * 256);
    ch[lane * 2]          = __halves2bfloat162(hh[0], hh[1]);
    ch[lane * 2 + 1]      = __halves2bfloat162(hh[2], hh[3]);
    ch[64 + lane * 2]     = __halves2bfloat162(hh[4], hh[5]);
    ch[64 + lane * 2 + 1] = __halves2bfloat162(hh[6], hh[7]);
    cl[lane * 2]          = __halves2bfloat162(ll[0], ll[1]);
    cl[lane * 2 + 1]      = __halves2bfloat162(ll[2], ll[3]);
    cl[64 + lane * 2]     = __halves2bfloat162(ll[4], ll[5]);
    cl[64 + lane * 2 + 1] = __halves2bfloat162(ll[6], ll[7]);
}

// ---------------------------------------------------------------------------
// wmma bf16 GEMM, W-resident + A double-buffered:
//   out = relu(Ah@Wh^T + Al@Wh^T + Ah@Wl^T)
// Full Wh/Wl staged in smem once; A streamed in 8 chunks of 32 cols with
// register prefetch; one __syncthreads per chunk. 256 threads, 2x4 warp grid.
// ---------------------------------------------------------------------------
#define WQSTR 264                   // W smem row stride (256 + 8)
#define AQSTR 40                    // A chunk row stride (32 + 8)
#define W_ELEMS (128 * WQSTR)       // 33792 bf16 per W matrix
#define ACH_ELEMS (128 * AQSTR)     // 5120 bf16 per A chunk matrix
#define ABUF_ELEMS (2 * ACH_ELEMS)  // Ah + Al per buffer
#define GSM_BYTES ((2 * W_ELEMS + 2 * ABUF_ELEMS) * 2)   // 176128 B

__global__ __launch_bounds__(256, 1)
void gemm_wmma_kernel(const __nv_bfloat16* __restrict__ Ah,
                      const __nv_bfloat16* __restrict__ Al,
                      const __nv_bfloat16* __restrict__ Wh,
                      const __nv_bfloat16* __restrict__ Wl,
                      float* __restrict__ out,
                      int Brows)
{
    extern __shared__ __align__(16) __nv_bfloat16 sm[];
    __nv_bfloat16* Whs = sm;
    __nv_bfloat16* Wls = sm + W_ELEMS;
    __nv_bfloat16* Abf = sm + 2 * W_ELEMS;   // [2][Ah(5120) | Al(5120)]

    int tid = threadIdx.x;
    int w = tid >> 5;
    int wm = w & 1, wn = w >> 1;
    int row0 = blockIdx.x * 128;
    int m0 = wm * 64, n0 = wn * 32;

    // stage full W (row-major [e][k], padded stride)
#pragma unroll
    for (int j = 0; j < 16; j++) {
        int i = j * 256 + tid;
        int r = i >> 5, c8 = (i & 31) * 8;
        *(uint4*)&Whs[r * WQSTR + c8] = *(const uint4*)&Wh[r * 256 + c8];
        *(uint4*)&Wls[r * WQSTR + c8] = *(const uint4*)&Wl[r * 256 + c8];
    }
    // stage A chunk 0
#pragma unroll
    for (int j = 0; j < 2; j++) {
        int i = j * 256 + tid;
        int r = i >> 2, c8 = (i & 3) * 8;
        uint4 vh = make_uint4(0, 0, 0, 0), vl = make_uint4(0, 0, 0, 0);
        if (row0 + r < Brows) {
            vh = *(const uint4*)&Ah[(size_t)(row0 + r) * 256 + c8];
            vl = *(const uint4*)&Al[(size_t)(row0 + r) * 256 + c8];
        }
        *(uint4*)&Abf[r * AQSTR + c8]              = vh;
        *(uint4*)&Abf[ACH_ELEMS + r * AQSTR + c8]  = vl;
    }
    __syncthreads();

    wmma::fragment<wmma::accumulator, 16, 16, 16, float> acc[4][2];
#pragma unroll
    for (int i = 0; i < 4; i++)
#pragma unroll
        for (int j = 0; j < 2; j++)
            wmma::fill_fragment(acc[i][j], 0.0f);

    int buf = 0;
    uint4 ph[2], pl[2];
#pragma unroll
    for (int chunk = 0; chunk < 8; chunk++) {
        // prefetch next A chunk into registers
        if (chunk < 7) {
            int kc = (chunk + 1) * 32;
#pragma unroll
            for (int j = 0; j < 2; j++) {
                int i = j * 256 + tid;
                int r = i >> 2, c8 = (i & 3) * 8;
                ph[j] = make_uint4(0, 0, 0, 0);
                pl[j] = make_uint4(0, 0, 0, 0);
                if (row0 + r < Brows) {
                    ph[j] = *(const uint4*)&Ah[(size_t)(row0 + r) * 256 + kc + c8];
                    pl[j] = *(const uint4*)&Al[(size_t)(row0 + r) * 256 + kc + c8];
                }
            }
        }

        const __nv_bfloat16* Ab = Abf + buf * ABUF_ELEMS;
#pragma unroll
        for (int kk = 0; kk < 32; kk += 16) {
            wmma::fragment<wmma::matrix_a, 16, 16, 16, __nv_bfloat16, wmma::row_major> ah[4], alf[4];
            wmma::fragment<wmma::matrix_b, 16, 16, 16, __nv_bfloat16, wmma::col_major> bh[2], bl[2];
#pragma unroll
            for (int i = 0; i < 4; i++) {
                wmma::load_matrix_sync(ah[i],  &Ab[(m0 + i * 16) * AQSTR + kk], AQSTR);
                wmma::load_matrix_sync(alf[i], &Ab[ACH_ELEMS + (m0 + i * 16) * AQSTR + kk], AQSTR);
            }
#pragma unroll
            for (int j = 0; j < 2; j++) {
                wmma::load_matrix_sync(bh[j], &Whs[(n0 + j * 16) * WQSTR + chunk * 32 + kk], WQSTR);
                wmma::load_matrix_sync(bl[j], &Wls[(n0 + j * 16) * WQSTR + chunk * 32 + kk], WQSTR);
            }
#pragma unroll
            for (int i = 0; i < 4; i++)
#pragma unroll
                for (int j = 0; j < 2; j++) {
                    wmma::mma_sync(acc[i][j], ah[i],  bh[j], acc[i][j]);
                    wmma::mma_sync(acc[i][j], alf[i], bh[j], acc[i][j]);
                    wmma::mma_sync(acc[i][j], ah[i],  bl[j], acc[i][j]);
                }
        }

        if (chunk < 7) {
            int nb = buf ^ 1;
#pragma unroll
            for (int j = 0; j < 2; j++) {
                int i = j * 256 + tid;
                int r = i >> 2, c8 = (i & 3) * 8;
                *(uint4*)&Abf[nb * ABUF_ELEMS + r * AQSTR + c8]             = ph[j];
                *(uint4*)&Abf[nb * ABUF_ELEMS + ACH_ELEMS + r * AQSTR + c8] = pl[j];
            }
            __syncthreads();
            buf = nb;
        }
    }

    // relu on fragments + direct store
#pragma unroll
    for (int i = 0; i < 4; i++) {
        int gr = row0 + m0 + i * 16;
        if (gr < Brows) {     // Brows % 16 == 0 -> whole tile valid
#pragma unroll
            for (int j = 0; j < 2; j++) {
#pragma unroll
                for (int e = 0; e < acc[i][j].num_elements; e++)
                    acc[i][j].x[e] = fmaxf(acc[i][j].x[e], 0.0f);
                wmma::store_matrix_sync(&out[(size_t)gr * FDIM + n0 + j * 16],
                                        acc[i][j], FDIM, wmma::mem_row_major);
            }
        }
    }
}

// ---------------------------------------------------------------------------
extern "C" void kernel_launch(void* const* d_in, const int* in_sizes, int n_in,
                              void* d_out, int out_size)
{
    const int*   nodes      = (const int*)d_in[0];
    const int*   neigh_idx  = (const int*)d_in[1];
    const float* self_table = (const float*)d_in[2];
    const float* neigh_tab  = (const float*)d_in[3];
    const float* center     = (const float*)d_in[4];
    const float* cmask      = (const float*)d_in[5];
    const float* weight     = (const float*)d_in[6];
    const float* alpha      = (const float*)d_in[7];
    float*       out        = (float*)d_out;

    int B = in_sizes[0];
    int N = in_sizes[3] / FDIM;

    float *pd, *c2;
    __half* prod;
    __nv_bfloat16 *ch, *cl, *wh, *wl;
    cudaGetSymbolAddress((void**)&prod, g_prod);
    cudaGetSymbolAddress((void**)&pd,   g_pdot);
    cudaGetSymbolAddress((void**)&c2,   g_c2);
    cudaGetSymbolAddress((void**)&ch,   g_comb_hi);
    cudaGetSymbolAddress((void**)&cl,   g_comb_lo);
    cudaGetSymbolAddress((void**)&wh,   g_w_hi);
    cudaGetSymbolAddress((void**)&wl,   g_w_lo);

    cudaFuncSetAttribute(gemm_wmma_kernel,
                         cudaFuncAttributeMaxDynamicSharedMemorySize, GSM_BYTES);

    c2_kernel<<<1, 512>>>(center, c2);
    wsplit_kernel<<<128, 256>>>(weight, wh, wl);
    precompute_kernel<<<(N + 63) / 64, 128>>>(neigh_tab, center, alpha, cmask,
                                              c2, prod, pd, N);
    row_kernel<<<(B + 7) / 8, 256>>>(nodes, neigh_idx, self_table, alpha,
                                     pd, prod, ch, cl, B);
    gemm_wmma_kernel<<<(B + 127) / 128, 256, GSM_BYTES>>>(ch, cl, wh, wl, out, B);
}